// round 16
// baseline (speedup 1.0000x reference)
#include <cuda_runtime.h>
#include <cuda_bf16.h>
#include <cstdint>

#define NROWS 8192
#define DIM   128
#define MARGIN 0.2f

#define BM 128
#define BN 128
#define NT 64               // 8192/128 tiles per dim
#define NTILES (NT * NT)    // 4096
#define GRIDP 304           // persistent CTAs (152 SMs x 2)

#define STB  32768          // stage: A 16KB + B 16KB (128 rows x 128B int8 each)
#define BOFF 16384
#define WSUM_OFF (3 * STB)  // 98304
#define SMEM_TOTAL (WSUM_OFF + 64)

// device scratch
__device__ float  g_a[NROWS];            // yy[i]-2<x_i,y_i>+margin  (exact fp32)
__device__ float  g_b[NROWS];            // yy[j]
__device__ float  g_sx2[NROWS];          // 2 * max|x_i| / 127
__device__ float  g_sy[NROWS];           //     max|y_j| / 127
__device__ double g_cta[GRIDP];
__device__ __align__(16) uint32_t g_xq[NROWS * 32];   // int8 rows, 128B each
__device__ __align__(16) uint32_t g_yq[NROWS * 32];

__device__ __forceinline__ uint32_t smem_u32(const void* p) {
    uint32_t a;
    asm("{ .reg .u64 t; cvta.to.shared.u64 t, %1; cvt.u32.u64 %0, t; }" : "=r"(a) : "l"(p));
    return a;
}
__device__ __forceinline__ void cp16(uint32_t dst, const void* src) {
    asm volatile("cp.async.cg.shared.global [%0], [%1], 16;" :: "r"(dst), "l"(src));
}
#define CP_COMMIT() asm volatile("cp.async.commit_group;" ::: "memory")
#define CP_WAIT(n)  asm volatile("cp.async.wait_group %0;" :: "n"(n) : "memory")

#define LDSM4(r, addr) \
    asm volatile("ldmatrix.sync.aligned.m8n8.x4.shared.b16 {%0,%1,%2,%3}, [%4];" \
        : "=r"((r)[0]), "=r"((r)[1]), "=r"((r)[2]), "=r"((r)[3]) : "r"(addr))

// int8 MMA: m16n8k32, exact int32 accumulation, 2x f16 rate on legacy path.
__device__ __forceinline__ void mma16832(int* c, const uint32_t* a,
                                         uint32_t b0, uint32_t b1) {
    asm("mma.sync.aligned.m16n8k32.row.col.s32.s8.s8.s32 "
        "{%0,%1,%2,%3}, {%4,%5,%6,%7}, {%8,%9}, {%0,%1,%2,%3};"
        : "+r"(c[0]), "+r"(c[1]), "+r"(c[2]), "+r"(c[3])
        : "r"(a[0]), "r"(a[1]), "r"(a[2]), "r"(a[3]), "r"(b0), "r"(b1));
}

__device__ __forceinline__ int q8(float v, float inv) {
    int q = __float2int_rn(v * inv);
    return max(-127, min(127, q));
}

// ---------------------------------------------------------------------------
// Precompute a[i], b[i], per-row scales, and int8-quantized rows.
// One warp per row.
// ---------------------------------------------------------------------------
__global__ void precompute_kernel(const float* __restrict__ x,
                                  const float* __restrict__ y) {
    int row  = blockIdx.x * 8 + (threadIdx.x >> 5);
    int lane = threadIdx.x & 31;

    float4 xv = reinterpret_cast<const float4*>(x + (size_t)row * DIM)[lane];
    float4 yv = reinterpret_cast<const float4*>(y + (size_t)row * DIM)[lane];

    float yy  = yv.x * yv.x + yv.y * yv.y + yv.z * yv.z + yv.w * yv.w;
    float dxy = xv.x * yv.x + xv.y * yv.y + xv.z * yv.z + xv.w * yv.w;
    float mx  = fmaxf(fmaxf(fabsf(xv.x), fabsf(xv.y)), fmaxf(fabsf(xv.z), fabsf(xv.w)));
    float my  = fmaxf(fmaxf(fabsf(yv.x), fabsf(yv.y)), fmaxf(fabsf(yv.z), fabsf(yv.w)));

    #pragma unroll
    for (int off = 16; off > 0; off >>= 1) {
        yy  += __shfl_xor_sync(0xFFFFFFFFu, yy,  off);
        dxy += __shfl_xor_sync(0xFFFFFFFFu, dxy, off);
        mx   = fmaxf(mx, __shfl_xor_sync(0xFFFFFFFFu, mx, off));
        my   = fmaxf(my, __shfl_xor_sync(0xFFFFFFFFu, my, off));
    }

    float invx = 127.0f / mx;       // rows of N(0,1) never all-zero
    float invy = 127.0f / my;

    int qx0 = q8(xv.x, invx), qx1 = q8(xv.y, invx), qx2 = q8(xv.z, invx), qx3 = q8(xv.w, invx);
    int qy0 = q8(yv.x, invy), qy1 = q8(yv.y, invy), qy2 = q8(yv.z, invy), qy3 = q8(yv.w, invy);

    g_xq[row * 32 + lane] = (uint32_t)(qx0 & 255) | ((uint32_t)(qx1 & 255) << 8) |
                            ((uint32_t)(qx2 & 255) << 16) | ((uint32_t)(qx3 & 255) << 24);
    g_yq[row * 32 + lane] = (uint32_t)(qy0 & 255) | ((uint32_t)(qy1 & 255) << 8) |
                            ((uint32_t)(qy2 & 255) << 16) | ((uint32_t)(qy3 & 255) << 24);

    if (lane == 0) {
        g_b[row]   = yy;
        g_a[row]   = yy - 2.0f * dxy + MARGIN;
        g_sx2[row] = 2.0f * mx / 127.0f;
        g_sy[row]  = my / 127.0f;
    }
}

// ---------------------------------------------------------------------------
// Persistent tile kernel. 304 CTAs x 256 threads, 2 CTAs/SM.
// One full 128x128 tile (K=128 int8) per pipeline step; 3-stage cp.async ring.
// Fragment addressing identical to the proven bf16 kernel (byte-pair view).
// ---------------------------------------------------------------------------
__device__ __forceinline__ void load_tile(uint32_t sb, int bid, int j, int tid) {
    int t   = bid + j * GRIDP;
    int gm0 = (t >> 6) * BM;
    int gn0 = (t & 63) * BN;
    uint32_t base = sb + (uint32_t)(j % 3) * STB;
    #pragma unroll
    for (int i = 0; i < 4; i++) {
        int f = i * 256 + tid;
        int r = f >> 3, cc = f & 7;
        uint32_t off = (uint32_t)(r * 128 + ((cc ^ (r & 7)) << 4));
        cp16(base + off,        (const char*)g_xq + (size_t)(gm0 + r) * 128 + cc * 16);
        cp16(base + BOFF + off, (const char*)g_yq + (size_t)(gn0 + r) * 128 + cc * 16);
    }
}

__device__ __forceinline__ void compute_tile(uint32_t base, int a_row, int a_kcl,
                                             int b_row, int b_kcl,
                                             int (&acc)[4][4][4]) {
    #pragma unroll
    for (int s = 0; s < 4; s++) {          // 4 x k32 = K128
        uint32_t af[4][4], bfr[2][4];
        #pragma unroll
        for (int mi = 0; mi < 4; mi++) {
            int m  = a_row + mi * 16;
            int kc = 2 * s + a_kcl;
            LDSM4(af[mi], base + (uint32_t)(m * 128 + ((kc ^ (m & 7)) << 4)));
        }
        #pragma unroll
        for (int nb = 0; nb < 2; nb++) {
            int n  = b_row + nb * 16;
            int kc = 2 * s + b_kcl;
            LDSM4(bfr[nb], base + BOFF + (uint32_t)(n * 128 + ((kc ^ (n & 7)) << 4)));
        }
        #pragma unroll
        for (int mi = 0; mi < 4; mi++) {
            #pragma unroll
            for (int nb = 0; nb < 2; nb++) {
                mma16832(acc[mi][2 * nb + 0], af[mi], bfr[nb][0], bfr[nb][1]);
                mma16832(acc[mi][2 * nb + 1], af[mi], bfr[nb][2], bfr[nb][3]);
            }
        }
    }
}

__global__ void __launch_bounds__(256, 2)
tile_kernel() {
    extern __shared__ char smem[];
    const uint32_t sb = smem_u32(smem);
    const int bid  = blockIdx.x;
    const int tid  = threadIdx.x;
    const int wid  = tid >> 5;
    const int lane = tid & 31;
    const int wm   = wid >> 2;         // 0..1
    const int wn   = wid & 3;          // 0..3

    const int a_row = wm * 64 + ((lane >> 3) & 1) * 8 + (lane & 7);
    const int a_kcl = lane >> 4;
    const int b_row = wn * 32 + ((lane >> 4) & 1) * 8 + (lane & 7);
    const int b_kcl = (lane >> 3) & 1;
    const int g  = lane >> 2;
    const int tg = lane & 3;

    const int nt = (NTILES - 1 - bid) / GRIDP + 1;   // tiles for this CTA (>=13)

    load_tile(sb, bid, 0, tid); CP_COMMIT();
    load_tile(sb, bid, 1, tid); CP_COMMIT();

    int acc[4][4][4];
    #pragma unroll
    for (int i = 0; i < 4; i++)
        #pragma unroll
        for (int jj = 0; jj < 4; jj++)
            #pragma unroll
            for (int q = 0; q < 4; q++) acc[i][jj][q] = 0;

    double s_run = 0.0;

    for (int j = 0; j < nt; j++) {
        CP_WAIT(1);                 // tile j resident (j+1 may be pending)
        __syncthreads();            // stage (j+2)%3's old data fully consumed
        if (j + 2 < nt) load_tile(sb, bid, j + 2, tid);
        CP_COMMIT();                // uniform group accounting

        compute_tile(sb + (uint32_t)(j % 3) * STB, a_row, a_kcl, b_row, b_kcl, acc);

        // fused epilogue on integer fragments
        int t   = bid + j * GRIDP;
        int gm0 = (t >> 6) * BM;
        int gn0 = (t & 63) * BN;
        float s = 0.0f;
        #pragma unroll
        for (int mi = 0; mi < 4; mi++) {
            int gi0 = gm0 + wm * 64 + mi * 16 + g;
            int gi1 = gi0 + 8;
            float a0 = __ldg(&g_a[gi0]),   a1 = __ldg(&g_a[gi1]);
            float f0 = __ldg(&g_sx2[gi0]), f1 = __ldg(&g_sx2[gi1]);
            #pragma unroll
            for (int ni = 0; ni < 4; ni++) {
                int gj0 = gn0 + wn * 32 + ni * 8 + tg * 2;
                int gj1 = gj0 + 1;
                float2 bb = __ldg(reinterpret_cast<const float2*>(&g_b[gj0]));
                float2 sy = __ldg(reinterpret_cast<const float2*>(&g_sy[gj0]));
                float v;
                v = fmaf(f0 * sy.x, (float)acc[mi][ni][0], a0 - bb.x); if (gi0 != gj0 && v > 0.0f) s += v;
                v = fmaf(f0 * sy.y, (float)acc[mi][ni][1], a0 - bb.y); if (gi0 != gj1 && v > 0.0f) s += v;
                v = fmaf(f1 * sy.x, (float)acc[mi][ni][2], a1 - bb.x); if (gi1 != gj0 && v > 0.0f) s += v;
                v = fmaf(f1 * sy.y, (float)acc[mi][ni][3], a1 - bb.y); if (gi1 != gj1 && v > 0.0f) s += v;
                acc[mi][ni][0] = 0; acc[mi][ni][1] = 0;
                acc[mi][ni][2] = 0; acc[mi][ni][3] = 0;
            }
        }
        s_run += (double)s;
    }

    // ---- per-CTA deterministic reduction (once) ----
    #pragma unroll
    for (int off = 16; off > 0; off >>= 1)
        s_run += __shfl_xor_sync(0xFFFFFFFFu, s_run, off);
    double* wsum = reinterpret_cast<double*>(smem + WSUM_OFF);
    if (lane == 0) wsum[wid] = s_run;
    __syncthreads();
    if (tid == 0) {
        double tsum = 0.0;
        #pragma unroll
        for (int w = 0; w < 8; w++) tsum += wsum[w];
        g_cta[bid] = tsum;
    }
}

// ---------------------------------------------------------------------------
// Final reduction: 304 doubles -> mean. Deterministic.
// ---------------------------------------------------------------------------
__global__ void reduce_kernel(float* __restrict__ out) {
    __shared__ double sh[8];
    int tid = threadIdx.x;   // 256 threads

    double s = 0.0;
    for (int t = tid; t < GRIDP; t += 256) s += g_cta[t];

    #pragma unroll
    for (int off = 16; off > 0; off >>= 1)
        s += __shfl_xor_sync(0xFFFFFFFFu, s, off);
    if ((tid & 31) == 0) sh[tid >> 5] = s;
    __syncthreads();
    if (tid == 0) {
        double t = 0.0;
        #pragma unroll
        for (int w = 0; w < 8; w++) t += sh[w];
        out[0] = (float)(t / ((double)NROWS * (double)NROWS));
    }
}

// ---------------------------------------------------------------------------
extern "C" void kernel_launch(void* const* d_in, const int* in_sizes, int n_in,
                              void* d_out, int out_size) {
    const float* x = (const float*)d_in[0];
    const float* y = (const float*)d_in[1];
    float* out = (float*)d_out;

    cudaFuncSetAttribute(tile_kernel,
                         cudaFuncAttributeMaxDynamicSharedMemorySize, SMEM_TOTAL);

    precompute_kernel<<<NROWS / 8, 256>>>(x, y);
    tile_kernel<<<GRIDP, 256, SMEM_TOTAL>>>();
    reduce_kernel<<<1, 256>>>(out);
}

// round 17
// speedup vs baseline: 2.3261x; 2.3261x over previous
#include <cuda_runtime.h>
#include <cuda_fp16.h>
#include <cstdint>

#define NROWS 8192
#define DIM   128
#define MARGIN 0.2f

#define BM 128
#define BN 256
#define KB 128              // f16 K per row
#define NT_M 64
#define NT_N 32
#define NTILES (NT_M * NT_N)    // 2048
#define GRIDP 304               // persistent CTAs (152 SMs x 2)

#define STB  49152          // stage: A 16KB + B 32KB (64-col chunk, 128B/row)
#define BOFF 16384
#define WSUM_OFF (2 * STB)  // 98304
#define SMEM_TOTAL (WSUM_OFF + 64)

// device scratch
__device__ float  g_a[NROWS];            // yy[i]-2<x_i,y_i>+margin
__device__ float  g_b[NROWS];            // yy[j]
__device__ double g_cta[GRIDP];
__device__ __align__(16) __half g_xh[NROWS * KB];
__device__ __align__(16) __half g_yh[NROWS * KB];

__device__ __forceinline__ uint32_t smem_u32(const void* p) {
    uint32_t a;
    asm("{ .reg .u64 t; cvta.to.shared.u64 t, %1; cvt.u32.u64 %0, t; }" : "=r"(a) : "l"(p));
    return a;
}
__device__ __forceinline__ void cp16(uint32_t dst, const void* src) {
    asm volatile("cp.async.cg.shared.global [%0], [%1], 16;" :: "r"(dst), "l"(src));
}
#define CP_COMMIT() asm volatile("cp.async.commit_group;" ::: "memory")
#define CP_WAIT(n)  asm volatile("cp.async.wait_group %0;" :: "n"(n) : "memory")

#define LDSM4(r, addr) \
    asm volatile("ldmatrix.sync.aligned.m8n8.x4.shared.b16 {%0,%1,%2,%3}, [%4];" \
        : "=r"((r)[0]), "=r"((r)[1]), "=r"((r)[2]), "=r"((r)[3]) : "r"(addr))

// f16 x f16 -> f16 accumulate: packed half2 accumulators (2 b32 regs per mma).
__device__ __forceinline__ void mma16816h(uint32_t* c, const uint32_t* a,
                                          uint32_t b0, uint32_t b1) {
    asm("mma.sync.aligned.m16n8k16.row.col.f16.f16.f16.f16 "
        "{%0,%1}, {%2,%3,%4,%5}, {%6,%7}, {%0,%1};"
        : "+r"(c[0]), "+r"(c[1])
        : "r"(a[0]), "r"(a[1]), "r"(a[2]), "r"(a[3]), "r"(b0), "r"(b1));
}

// ---------------------------------------------------------------------------
// Precompute a[i], b[i] and f16 rows. One warp per row.
// ---------------------------------------------------------------------------
__global__ void precompute_kernel(const float* __restrict__ x,
                                  const float* __restrict__ y) {
    int row  = blockIdx.x * 8 + (threadIdx.x >> 5);
    int lane = threadIdx.x & 31;

    float4 xv = reinterpret_cast<const float4*>(x + (size_t)row * DIM)[lane];
    float4 yv = reinterpret_cast<const float4*>(y + (size_t)row * DIM)[lane];

    float yy  = yv.x * yv.x + yv.y * yv.y + yv.z * yv.z + yv.w * yv.w;
    float dxy = xv.x * yv.x + xv.y * yv.y + xv.z * yv.z + xv.w * yv.w;

    __half2* xr = reinterpret_cast<__half2*>(g_xh + (size_t)row * KB);
    __half2* yr = reinterpret_cast<__half2*>(g_yh + (size_t)row * KB);
    xr[lane * 2 + 0] = __floats2half2_rn(xv.x, xv.y);
    xr[lane * 2 + 1] = __floats2half2_rn(xv.z, xv.w);
    yr[lane * 2 + 0] = __floats2half2_rn(yv.x, yv.y);
    yr[lane * 2 + 1] = __floats2half2_rn(yv.z, yv.w);

    #pragma unroll
    for (int off = 16; off > 0; off >>= 1) {
        yy  += __shfl_xor_sync(0xFFFFFFFFu, yy,  off);
        dxy += __shfl_xor_sync(0xFFFFFFFFu, dxy, off);
    }
    if (lane == 0) {
        g_b[row] = yy;
        g_a[row] = yy - 2.0f * dxy + MARGIN;
    }
}

// ---------------------------------------------------------------------------
// Persistent tile kernel. 304 CTAs x 256 threads, 2 CTAs/SM.
// Block tile 128x256, 8 warps with 64x64 warp tiles, f16 accumulation.
// Continuous 2-stage cp.async ring over 64-col K-chunks (2 per tile).
// ---------------------------------------------------------------------------
__device__ __forceinline__ void load_chunk(uint32_t sb, int bid, int cj, int tid) {
    int t   = bid + (cj >> 1) * GRIDP;
    int gm0 = (t >> 5) * BM;         // t / 32
    int gn0 = (t & 31) * BN;
    int k0  = (cj & 1) * 64;
    uint32_t base = sb + (uint32_t)(cj & 1) * STB;
    #pragma unroll
    for (int i = 0; i < 4; i++) {    // A: 128 rows x 128B
        int f = i * 256 + tid;
        int r = f >> 3, cc = f & 7;
        uint32_t off = (uint32_t)(r * 128 + ((cc ^ (r & 7)) << 4));
        cp16(base + off, g_xh + (size_t)(gm0 + r) * KB + k0 + cc * 8);
    }
    #pragma unroll
    for (int i = 0; i < 8; i++) {    // B: 256 rows x 128B
        int f = i * 256 + tid;
        int r = f >> 3, cc = f & 7;
        uint32_t off = (uint32_t)(r * 128 + ((cc ^ (r & 7)) << 4));
        cp16(base + BOFF + off, g_yh + (size_t)(gn0 + r) * KB + k0 + cc * 8);
    }
}

__device__ __forceinline__ void compute_chunk(uint32_t base, int a_row, int a_kcl,
                                              int b_row, int b_kcl,
                                              uint32_t (&acc)[4][8][2]) {
    #pragma unroll
    for (int s = 0; s < 4; s++) {
        uint32_t af[4][4], bfr[4][4];
        #pragma unroll
        for (int mi = 0; mi < 4; mi++) {
            int m  = a_row + mi * 16;
            int kc = 2 * s + a_kcl;
            LDSM4(af[mi], base + (uint32_t)(m * 128 + ((kc ^ (m & 7)) << 4)));
        }
        #pragma unroll
        for (int nb = 0; nb < 4; nb++) {
            int n  = b_row + nb * 16;
            int kc = 2 * s + b_kcl;
            LDSM4(bfr[nb], base + BOFF + (uint32_t)(n * 128 + ((kc ^ (n & 7)) << 4)));
        }
        #pragma unroll
        for (int mi = 0; mi < 4; mi++) {
            #pragma unroll
            for (int nb = 0; nb < 4; nb++) {
                mma16816h(acc[mi][2 * nb + 0], af[mi], bfr[nb][0], bfr[nb][1]);
                mma16816h(acc[mi][2 * nb + 1], af[mi], bfr[nb][2], bfr[nb][3]);
            }
        }
    }
}

__global__ void __launch_bounds__(256, 2)
tile_kernel() {
    extern __shared__ char smem[];
    const uint32_t sb = smem_u32(smem);
    const int bid  = blockIdx.x;
    const int tid  = threadIdx.x;
    const int wid  = tid >> 5;
    const int lane = tid & 31;
    const int wm   = wid >> 2;         // 0..1 -> 64-row slice
    const int wn   = wid & 3;          // 0..3 -> 64-col slice

    const int a_row = wm * 64 + ((lane >> 3) & 1) * 8 + (lane & 7);
    const int a_kcl = lane >> 4;
    const int b_row = wn * 64 + ((lane >> 4) & 1) * 8 + (lane & 7);
    const int b_kcl = (lane >> 3) & 1;
    const int g  = lane >> 2;
    const int tg = lane & 3;

    const int nt  = (NTILES - 1 - bid) / GRIDP + 1;   // tiles for this CTA
    const int nch = 2 * nt;

    load_chunk(sb, bid, 0, tid); CP_COMMIT();
    load_chunk(sb, bid, 1, tid); CP_COMMIT();

    uint32_t acc[4][8][2];
    #pragma unroll
    for (int i = 0; i < 4; i++)
        #pragma unroll
        for (int jj = 0; jj < 8; jj++) { acc[i][jj][0] = 0u; acc[i][jj][1] = 0u; }

    double s_run = 0.0;

    for (int j = 0; j < nch; j++) {
        CP_WAIT(1);                 // chunk j resident (j+1 may be pending)
        __syncthreads();
        compute_chunk(sb + (uint32_t)(j & 1) * STB, a_row, a_kcl, b_row, b_kcl, acc);
        __syncthreads();            // all warps done reading stage j&1
        if (j + 2 < nch) load_chunk(sb, bid, j + 2, tid);
        CP_COMMIT();                // uniform group accounting

        if (j & 1) {
            // tile (j>>1) finished: epilogue on packed f16 fragments
            int t   = bid + (j >> 1) * GRIDP;
            int gm0 = (t >> 5) * BM;
            int gn0 = (t & 31) * BN;
            float s = 0.0f;
            #pragma unroll
            for (int mi = 0; mi < 4; mi++) {
                int gi0 = gm0 + wm * 64 + mi * 16 + g;
                int gi1 = gi0 + 8;
                float a0 = __ldg(&g_a[gi0]);
                float a1 = __ldg(&g_a[gi1]);
                #pragma unroll
                for (int ni = 0; ni < 8; ni++) {
                    int gj0 = gn0 + wn * 64 + ni * 8 + tg * 2;
                    int gj1 = gj0 + 1;
                    float2 bb = __ldg(reinterpret_cast<const float2*>(&g_b[gj0]));
                    float2 s0 = __half22float2(*reinterpret_cast<__half2*>(&acc[mi][ni][0]));
                    float2 s1 = __half22float2(*reinterpret_cast<__half2*>(&acc[mi][ni][1]));
                    float v;
                    v = fmaf(2.0f, s0.x, a0 - bb.x); if (gi0 != gj0 && v > 0.0f) s += v;
                    v = fmaf(2.0f, s0.y, a0 - bb.y); if (gi0 != gj1 && v > 0.0f) s += v;
                    v = fmaf(2.0f, s1.x, a1 - bb.x); if (gi1 != gj0 && v > 0.0f) s += v;
                    v = fmaf(2.0f, s1.y, a1 - bb.y); if (gi1 != gj1 && v > 0.0f) s += v;
                    acc[mi][ni][0] = 0u; acc[mi][ni][1] = 0u;
                }
            }
            s_run += (double)s;
        }
    }

    // ---- per-CTA deterministic reduction (once) ----
    #pragma unroll
    for (int off = 16; off > 0; off >>= 1)
        s_run += __shfl_xor_sync(0xFFFFFFFFu, s_run, off);
    double* wsum = reinterpret_cast<double*>(smem + WSUM_OFF);
    if (lane == 0) wsum[wid] = s_run;
    __syncthreads();
    if (tid == 0) {
        double tsum = 0.0;
        #pragma unroll
        for (int w = 0; w < 8; w++) tsum += wsum[w];
        g_cta[bid] = tsum;
    }
}

// ---------------------------------------------------------------------------
// Final reduction: 304 doubles -> mean. Deterministic.
// ---------------------------------------------------------------------------
__global__ void reduce_kernel(float* __restrict__ out) {
    __shared__ double sh[8];
    int tid = threadIdx.x;   // 256 threads

    double s = 0.0;
    for (int t = tid; t < GRIDP; t += 256) s += g_cta[t];

    #pragma unroll
    for (int off = 16; off > 0; off >>= 1)
        s += __shfl_xor_sync(0xFFFFFFFFu, s, off);
    if ((tid & 31) == 0) sh[tid >> 5] = s;
    __syncthreads();
    if (tid == 0) {
        double t = 0.0;
        #pragma unroll
        for (int w = 0; w < 8; w++) t += sh[w];
        out[0] = (float)(t / ((double)NROWS * (double)NROWS));
    }
}

// ---------------------------------------------------------------------------
extern "C" void kernel_launch(void* const* d_in, const int* in_sizes, int n_in,
                              void* d_out, int out_size) {
    const float* x = (const float*)d_in[0];
    const float* y = (const float*)d_in[1];
    float* out = (float*)d_out;

    cudaFuncSetAttribute(tile_kernel,
                         cudaFuncAttributeMaxDynamicSharedMemorySize, SMEM_TOTAL);

    precompute_kernel<<<NROWS / 8, 256>>>(x, y);
    tile_kernel<<<GRIDP, 256, SMEM_TOTAL>>>();
    reduce_kernel<<<1, 256>>>(out);
}